// round 2
// baseline (speedup 1.0000x reference)
#include <cuda_runtime.h>
#include <cuda_bf16.h>
#include <cstdint>

// ================================================================
// out[8192,4096] = A[8192,4096] (K-major) * W[4096,4096] (K-major)^T
// Fallback-PTX path (compute_103 target: no tcgen05/TMEM):
//   tf32 mma.sync m16n8k8 + cp.async 4-stage pipeline.
//   CTA tile 128x128x32, 8 warps (2M x 4N), warp tile 64x32.
//   Fragments rounded with cvt.rna.tf32.f32 (avoids truncation bias).
// ================================================================

#define M_DIM 8192
#define N_DIM 4096
#define K_DIM 4096

#define BM 128
#define BN 128
#define BK 32                       // floats per K chunk
#define STAGES 4
#define NCHUNK (K_DIM / BK)         // 128

#define ROW_PAD   36                // 32 + 4 floats padding (16B-aligned rows)
#define MAT_FLOATS (BM * ROW_PAD)   // 4608 floats per matrix tile
#define STAGE_FLOATS (2 * MAT_FLOATS)
#define SMEM_BYTES (STAGES * STAGE_FLOATS * 4)   // 147456

__device__ __forceinline__ uint32_t smem_u32(const void* p) {
    uint32_t a;
    asm("{ .reg .u64 t; cvta.to.shared.u64 t, %1; cvt.u32.u64 %0, t; }" : "=r"(a) : "l"(p));
    return a;
}

__device__ __forceinline__ void cp_async16(uint32_t s, const void* g) {
    asm volatile("cp.async.cg.shared.global [%0], [%1], 16;" :: "r"(s), "l"(g));
}
__device__ __forceinline__ void cp_commit() {
    asm volatile("cp.async.commit_group;" ::: "memory");
}
template <int N>
__device__ __forceinline__ void cp_wait() {
    asm volatile("cp.async.wait_group %0;" :: "n"(N) : "memory");
}

__device__ __forceinline__ uint32_t f2tf32(float x) {
    uint32_t r;
    asm("cvt.rna.tf32.f32 %0, %1;" : "=r"(r) : "f"(x));
    return r;
}

__device__ __forceinline__ void mma_tf32(float c[4],
                                         const uint32_t a[4],
                                         const uint32_t b[2]) {
    asm volatile(
        "mma.sync.aligned.m16n8k8.row.col.f32.tf32.tf32.f32 "
        "{%0,%1,%2,%3}, {%4,%5,%6,%7}, {%8,%9}, {%0,%1,%2,%3};"
        : "+f"(c[0]), "+f"(c[1]), "+f"(c[2]), "+f"(c[3])
        : "r"(a[0]), "r"(a[1]), "r"(a[2]), "r"(a[3]), "r"(b[0]), "r"(b[1]));
}

extern __shared__ float smemf[];

__global__ void __launch_bounds__(256, 1) agg_gemm_kernel(
    const float* __restrict__ A,     // [M, K]
    const float* __restrict__ W,     // [N, K]
    float* __restrict__ out)         // [M, N]
{
    const int t = threadIdx.x;
    const int wid = t >> 5;
    const int lane = t & 31;
    const int wm = wid & 1;          // warp M index (0..1)
    const int wn = wid >> 1;         // warp N index (0..3)
    const int g = lane >> 2;         // group 0..7
    const int tig = lane & 3;        // thread-in-group 0..3

    const int m0 = blockIdx.y * BM;
    const int n0 = blockIdx.x * BN;

    const uint32_t sb = smem_u32(smemf);

    // copy-thread mapping: 8 x 16B segments per thread per stage
    const int seg = t & 7;           // col segment (seg*4 floats)
    const int rbase = t >> 3;        // row base (0..31), rows rbase + 32*i

    // ---------------- pipeline loader ----------------
    auto load_stage = [&](int stage, int c) {
        const int k0 = c * BK;
        uint32_t sA = sb + (uint32_t)(stage * STAGE_FLOATS) * 4u;
        uint32_t sB = sA + (uint32_t)MAT_FLOATS * 4u;
        #pragma unroll
        for (int i = 0; i < 4; i++) {
            int row = rbase + i * 32;
            cp_async16(sA + (uint32_t)(row * ROW_PAD + seg * 4) * 4u,
                       A + (size_t)(m0 + row) * K_DIM + k0 + seg * 4);
        }
        #pragma unroll
        for (int i = 0; i < 4; i++) {
            int row = rbase + i * 32;
            cp_async16(sB + (uint32_t)(row * ROW_PAD + seg * 4) * 4u,
                       W + (size_t)(n0 + row) * K_DIM + k0 + seg * 4);
        }
    };

    float acc[4][4][4];
    #pragma unroll
    for (int mi = 0; mi < 4; mi++)
        #pragma unroll
        for (int ni = 0; ni < 4; ni++)
            #pragma unroll
            for (int q = 0; q < 4; q++) acc[mi][ni][q] = 0.0f;

    // prologue: fill STAGES-1 stages
    #pragma unroll
    for (int ps = 0; ps < STAGES - 1; ps++) {
        load_stage(ps, ps);
        cp_commit();
    }

    for (int c = 0; c < NCHUNK; c++) {
        cp_wait<STAGES - 2>();
        __syncthreads();

        // issue next fetch (into the stage consumed last iteration)
        const int fetch = c + STAGES - 1;
        if (fetch < NCHUNK) load_stage(fetch & (STAGES - 1), fetch);
        cp_commit();

        // compute chunk c from its stage
        const int s = c & (STAGES - 1);
        const float* As = smemf + s * STAGE_FLOATS;
        const float* Bs = As + MAT_FLOATS;

        #pragma unroll
        for (int ki = 0; ki < 4; ki++) {
            const int cc = ki * 8 + tig;
            uint32_t a[4][4], b[4][2];
            #pragma unroll
            for (int mi = 0; mi < 4; mi++) {
                const int r = wm * 64 + mi * 16 + g;
                a[mi][0] = f2tf32(As[r * ROW_PAD + cc]);
                a[mi][1] = f2tf32(As[(r + 8) * ROW_PAD + cc]);
                a[mi][2] = f2tf32(As[r * ROW_PAD + cc + 4]);
                a[mi][3] = f2tf32(As[(r + 8) * ROW_PAD + cc + 4]);
            }
            #pragma unroll
            for (int ni = 0; ni < 4; ni++) {
                const int r = wn * 32 + ni * 8 + g;
                b[ni][0] = f2tf32(Bs[r * ROW_PAD + cc]);
                b[ni][1] = f2tf32(Bs[r * ROW_PAD + cc + 4]);
            }
            #pragma unroll
            for (int mi = 0; mi < 4; mi++)
                #pragma unroll
                for (int ni = 0; ni < 4; ni++)
                    mma_tf32(acc[mi][ni], a[mi], b[ni]);
        }
        __syncthreads();
    }

    // ---------------- epilogue ----------------
    #pragma unroll
    for (int mi = 0; mi < 4; mi++) {
        const int row = m0 + wm * 64 + mi * 16 + g;
        #pragma unroll
        for (int ni = 0; ni < 4; ni++) {
            const int col = n0 + wn * 32 + ni * 8 + 2 * tig;
            float2 lo = make_float2(acc[mi][ni][0], acc[mi][ni][1]);
            float2 hi = make_float2(acc[mi][ni][2], acc[mi][ni][3]);
            *reinterpret_cast<float2*>(out + (size_t)row * N_DIM + col) = lo;
            *reinterpret_cast<float2*>(out + (size_t)(row + 8) * N_DIM + col) = hi;
        }
    }
}

extern "C" void kernel_launch(void* const* d_in, const int* in_sizes, int n_in,
                              void* d_out, int out_size) {
    const float* A = (const float*)d_in[0];   // [8,1024,4096] contiguous = [8192,4096]
    const float* W = (const float*)d_in[1];   // [4096,4096] K-major
    float* out = (float*)d_out;

    cudaFuncSetAttribute(agg_gemm_kernel,
                         cudaFuncAttributeMaxDynamicSharedMemorySize, SMEM_BYTES);

    dim3 grid(N_DIM / BN, M_DIM / BM);   // (32, 64) — x-fastest: A tile reused, W streams via L2
    agg_gemm_kernel<<<grid, 256, SMEM_BYTES>>>(A, W, out);
}

// round 3
// speedup vs baseline: 1.1964x; 1.1964x over previous
#include <cuda_runtime.h>
#include <cuda_bf16.h>
#include <cstdint>

// ================================================================
// out[8192,4096] = A[8192,4096] (K-major) * W[4096,4096] (K-major)^T
// tf32 mma.sync m16n8k8, cp.async 3-stage pipeline, 2 CTAs/SM.
// tf32 rna-rounding hoisted into a pre-pass (scratch device globals).
// ================================================================

#define M_DIM 8192
#define N_DIM 4096
#define K_DIM 4096

#define BM 128
#define BN 128
#define BK 32
#define STAGES 3
#define NCHUNK (K_DIM / BK)         // 128

#define ROW_PAD 36
#define MAT_FLOATS (BM * ROW_PAD)               // 4608
#define STAGE_FLOATS (2 * MAT_FLOATS)
#define SMEM_BYTES (STAGES * STAGE_FLOATS * 4)  // 110592 -> 2 CTAs/SM

// tf32-rounded copies
__device__ __align__(1024) float g_A[(size_t)M_DIM * K_DIM];
__device__ __align__(1024) float g_B[(size_t)N_DIM * K_DIM];

__device__ __forceinline__ uint32_t smem_u32(const void* p) {
    uint32_t a;
    asm("{ .reg .u64 t; cvta.to.shared.u64 t, %1; cvt.u32.u64 %0, t; }" : "=r"(a) : "l"(p));
    return a;
}
__device__ __forceinline__ void cp_async16(uint32_t s, const void* g) {
    asm volatile("cp.async.cg.shared.global [%0], [%1], 16;" :: "r"(s), "l"(g));
}
__device__ __forceinline__ void cp_commit() {
    asm volatile("cp.async.commit_group;" ::: "memory");
}
template <int N>
__device__ __forceinline__ void cp_wait() {
    asm volatile("cp.async.wait_group %0;" :: "n"(N) : "memory");
}
__device__ __forceinline__ void mma_tf32(float c[4],
                                         const uint32_t a[4],
                                         const uint32_t b[2]) {
    asm volatile(
        "mma.sync.aligned.m16n8k8.row.col.f32.tf32.tf32.f32 "
        "{%0,%1,%2,%3}, {%4,%5,%6,%7}, {%8,%9}, {%0,%1,%2,%3};"
        : "+f"(c[0]), "+f"(c[1]), "+f"(c[2]), "+f"(c[3])
        : "r"(a[0]), "r"(a[1]), "r"(a[2]), "r"(a[3]), "r"(b[0]), "r"(b[1]));
}

// ---------------- pre-pass: fp32 -> tf32 (round-to-nearest) ----------------
__global__ void __launch_bounds__(256) cvt_tf32_kernel(
    const float4* __restrict__ in, uint4* __restrict__ out, int n4)
{
    int stride = gridDim.x * blockDim.x;
    for (int i = blockIdx.x * blockDim.x + threadIdx.x; i < n4; i += stride) {
        float4 v = in[i];
        uint4 o;
        asm("cvt.rna.tf32.f32 %0, %1;" : "=r"(o.x) : "f"(v.x));
        asm("cvt.rna.tf32.f32 %0, %1;" : "=r"(o.y) : "f"(v.y));
        asm("cvt.rna.tf32.f32 %0, %1;" : "=r"(o.z) : "f"(v.z));
        asm("cvt.rna.tf32.f32 %0, %1;" : "=r"(o.w) : "f"(v.w));
        out[i] = o;
    }
}

extern __shared__ float smemf[];

__global__ void __launch_bounds__(256, 2) agg_gemm_kernel(
    const float* __restrict__ A,     // [M, K], tf32-rounded
    const float* __restrict__ W,     // [N, K], tf32-rounded
    float* __restrict__ out)         // [M, N]
{
    const int t = threadIdx.x;
    const int wid = t >> 5;
    const int lane = t & 31;
    const int wm = wid & 1;          // warp M index (0..1)
    const int wn = wid >> 1;         // warp N index (0..3)
    const int g = lane >> 2;         // group 0..7
    const int tig = lane & 3;        // thread-in-group 0..3

    const int m0 = blockIdx.y * BM;
    const int n0 = blockIdx.x * BN;

    const uint32_t sb = smem_u32(smemf);

    const int seg = t & 7;           // 16B column segment
    const int rbase = t >> 3;        // row base (0..31)

    auto load_stage = [&](int stage, int c) {
        const int k0 = c * BK;
        uint32_t sA = sb + (uint32_t)(stage * STAGE_FLOATS) * 4u;
        uint32_t sB = sA + (uint32_t)MAT_FLOATS * 4u;
        #pragma unroll
        for (int i = 0; i < 4; i++) {
            int row = rbase + i * 32;
            cp_async16(sA + (uint32_t)(row * ROW_PAD + seg * 4) * 4u,
                       A + (size_t)(m0 + row) * K_DIM + k0 + seg * 4);
        }
        #pragma unroll
        for (int i = 0; i < 4; i++) {
            int row = rbase + i * 32;
            cp_async16(sB + (uint32_t)(row * ROW_PAD + seg * 4) * 4u,
                       W + (size_t)(n0 + row) * K_DIM + k0 + seg * 4);
        }
    };

    float acc[4][4][4];
    #pragma unroll
    for (int mi = 0; mi < 4; mi++)
        #pragma unroll
        for (int ni = 0; ni < 4; ni++)
            #pragma unroll
            for (int q = 0; q < 4; q++) acc[mi][ni][q] = 0.0f;

    // prologue: fill STAGES-1 stages
    #pragma unroll
    for (int ps = 0; ps < STAGES - 1; ps++) {
        load_stage(ps, ps);
        cp_commit();
    }

    int cstage = 0;                      // compute stage for chunk c
    int fstage = STAGES - 1;             // fetch stage for chunk c+STAGES-1
    for (int c = 0; c < NCHUNK; c++) {
        cp_wait<STAGES - 2>();
        __syncthreads();

        const int fetch = c + STAGES - 1;
        if (fetch < NCHUNK) load_stage(fstage, fetch);
        cp_commit();
        if (++fstage == STAGES) fstage = 0;

        const float* As = smemf + cstage * STAGE_FLOATS;
        const float* Bs = As + MAT_FLOATS;
        if (++cstage == STAGES) cstage = 0;

        #pragma unroll
        for (int ki = 0; ki < 4; ki++) {
            const int cc = ki * 8 + tig;
            uint32_t a[4][4], b[4][2];
            #pragma unroll
            for (int mi = 0; mi < 4; mi++) {
                const int r = wm * 64 + mi * 16 + g;
                a[mi][0] = __float_as_uint(As[r * ROW_PAD + cc]);
                a[mi][1] = __float_as_uint(As[(r + 8) * ROW_PAD + cc]);
                a[mi][2] = __float_as_uint(As[r * ROW_PAD + cc + 4]);
                a[mi][3] = __float_as_uint(As[(r + 8) * ROW_PAD + cc + 4]);
            }
            #pragma unroll
            for (int ni = 0; ni < 4; ni++) {
                const int r = wn * 32 + ni * 8 + g;
                b[ni][0] = __float_as_uint(Bs[r * ROW_PAD + cc]);
                b[ni][1] = __float_as_uint(Bs[r * ROW_PAD + cc + 4]);
            }
            #pragma unroll
            for (int mi = 0; mi < 4; mi++)
                #pragma unroll
                for (int ni = 0; ni < 4; ni++)
                    mma_tf32(acc[mi][ni], a[mi], b[ni]);
        }
        __syncthreads();
    }

    // ---------------- epilogue ----------------
    #pragma unroll
    for (int mi = 0; mi < 4; mi++) {
        const int row = m0 + wm * 64 + mi * 16 + g;
        #pragma unroll
        for (int ni = 0; ni < 4; ni++) {
            const int col = n0 + wn * 32 + ni * 8 + 2 * tig;
            float2 lo = make_float2(acc[mi][ni][0], acc[mi][ni][1]);
            float2 hi = make_float2(acc[mi][ni][2], acc[mi][ni][3]);
            *reinterpret_cast<float2*>(out + (size_t)row * N_DIM + col) = lo;
            *reinterpret_cast<float2*>(out + (size_t)(row + 8) * N_DIM + col) = hi;
        }
    }
}

extern "C" void kernel_launch(void* const* d_in, const int* in_sizes, int n_in,
                              void* d_out, int out_size) {
    const float* A_in = (const float*)d_in[0];   // [8,1024,4096] = [8192,4096]
    const float* W_in = (const float*)d_in[1];   // [4096,4096] K-major
    float* out = (float*)d_out;

    void *pA = nullptr, *pB = nullptr;
    cudaGetSymbolAddress(&pA, g_A);
    cudaGetSymbolAddress(&pB, g_B);

    cudaFuncSetAttribute(agg_gemm_kernel,
                         cudaFuncAttributeMaxDynamicSharedMemorySize, SMEM_BYTES);

    cvt_tf32_kernel<<<1184, 256>>>((const float4*)A_in, (uint4*)pA,
                                   (int)(((size_t)M_DIM * K_DIM) / 4));
    cvt_tf32_kernel<<<1184, 256>>>((const float4*)W_in, (uint4*)pB,
                                   (int)(((size_t)N_DIM * K_DIM) / 4));

    dim3 grid(N_DIM / BN, M_DIM / BM);   // (32, 64)
    agg_gemm_kernel<<<grid, 256, SMEM_BYTES>>>((const float*)pA, (const float*)pB, out);
}

// round 4
// speedup vs baseline: 2.6246x; 2.1938x over previous
#include <cuda_runtime.h>
#include <cuda_fp16.h>
#include <cstdint>

// ================================================================
// out[8192,4096] = A[8192,4096] (K-major) * W[4096,4096] (K-major)^T
// fp16 mma.sync m16n8k16 (same 10-bit mantissa as tf32 -> same rel_err),
// ldmatrix fragment loads, XOR-swizzled smem, cp.async 3-stage pipeline,
// 2 CTAs/SM. fp16 conversion hoisted into a pre-pass.
// ================================================================

#define M_DIM 8192
#define N_DIM 4096
#define K_DIM 4096

#define BM 128
#define BN 128
#define BK 64                        // fp16 elems per K chunk = 128 B/row
#define STAGES 3
#define NCHUNK (K_DIM / BK)          // 64

#define A_STAGE_BYTES (BM * 128)     // 16384
#define B_STAGE_BYTES (BN * 128)     // 16384
#define STAGE_BYTES   (A_STAGE_BYTES + B_STAGE_BYTES)      // 32768
#define SMEM_BYTES    (STAGES * STAGE_BYTES)               // 98304 -> 2 CTAs/SM

// fp16 copies of the operands
__device__ __align__(1024) __half g_A[(size_t)M_DIM * K_DIM];
__device__ __align__(1024) __half g_B[(size_t)N_DIM * K_DIM];

__device__ __forceinline__ uint32_t smem_u32(const void* p) {
    uint32_t a;
    asm("{ .reg .u64 t; cvta.to.shared.u64 t, %1; cvt.u32.u64 %0, t; }" : "=r"(a) : "l"(p));
    return a;
}
__device__ __forceinline__ void cp_async16(uint32_t s, const void* g) {
    asm volatile("cp.async.cg.shared.global [%0], [%1], 16;" :: "r"(s), "l"(g));
}
__device__ __forceinline__ void cp_commit() {
    asm volatile("cp.async.commit_group;" ::: "memory");
}
template <int N>
__device__ __forceinline__ void cp_wait() {
    asm volatile("cp.async.wait_group %0;" :: "n"(N) : "memory");
}
__device__ __forceinline__ void ldsm_x4(uint32_t r[4], uint32_t addr) {
    asm volatile("ldmatrix.sync.aligned.m8n8.x4.shared.b16 {%0,%1,%2,%3}, [%4];"
                 : "=r"(r[0]), "=r"(r[1]), "=r"(r[2]), "=r"(r[3]) : "r"(addr));
}
__device__ __forceinline__ void mma_f16(float c[4], const uint32_t a[4],
                                        uint32_t b0, uint32_t b1) {
    asm volatile(
        "mma.sync.aligned.m16n8k16.row.col.f32.f16.f16.f32 "
        "{%0,%1,%2,%3}, {%4,%5,%6,%7}, {%8,%9}, {%0,%1,%2,%3};"
        : "+f"(c[0]), "+f"(c[1]), "+f"(c[2]), "+f"(c[3])
        : "r"(a[0]), "r"(a[1]), "r"(a[2]), "r"(a[3]), "r"(b0), "r"(b1));
}

// ---------------- pre-pass: fp32 -> fp16 (round-to-nearest) ----------------
__global__ void __launch_bounds__(256) cvt_f16_kernel(
    const float4* __restrict__ in, __half2* __restrict__ out, int n4)
{
    int stride = gridDim.x * blockDim.x;
    for (int i = blockIdx.x * blockDim.x + threadIdx.x; i < n4; i += stride) {
        float4 v = in[i];
        out[2 * i]     = __floats2half2_rn(v.x, v.y);
        out[2 * i + 1] = __floats2half2_rn(v.z, v.w);
    }
}

extern __shared__ char smemc[];

__global__ void __launch_bounds__(256, 2) agg_gemm_kernel(
    const __half* __restrict__ A,    // [M, K] fp16
    const __half* __restrict__ W,    // [N, K] fp16
    float* __restrict__ out)         // [M, N] fp32
{
    const int t = threadIdx.x;
    const int wid = t >> 5;
    const int lane = t & 31;
    const int wm = wid & 1;          // warp M (0..1), 64-row tile
    const int wn = wid >> 1;         // warp N (0..3), 32-col tile
    const int g = lane >> 2;
    const int tig = lane & 3;

    const int m0 = blockIdx.y * BM;
    const int n0 = blockIdx.x * BN;

    const uint32_t sb = smem_u32(smemc);

    // cp.async mapping: thread t covers (row = t/8 + 32*i, chunk = t%8), 16B chunks
    const int seg = t & 7;
    const int rbase = t >> 3;

    auto load_stage = [&](int stage, int c) {
        const int k0 = c * BK;
        const uint32_t sA = sb + (uint32_t)stage * STAGE_BYTES;
        const uint32_t sB = sA + A_STAGE_BYTES;
        #pragma unroll
        for (int i = 0; i < 4; i++) {
            const int row = rbase + i * 32;
            const uint32_t soff = (uint32_t)row * 128u + (uint32_t)((seg ^ (row & 7)) * 16);
            cp_async16(sA + soff, A + (size_t)(m0 + row) * K_DIM + k0 + seg * 8);
            cp_async16(sB + soff, W + (size_t)(n0 + row) * K_DIM + k0 + seg * 8);
        }
    };

    float acc[4][4][4];
    #pragma unroll
    for (int mi = 0; mi < 4; mi++)
        #pragma unroll
        for (int ni = 0; ni < 4; ni++)
            #pragma unroll
            for (int q = 0; q < 4; q++) acc[mi][ni][q] = 0.0f;

    // ldmatrix lane addressing (bytes, pre-swizzle row part):
    //   A: row = wm*64 + mi*16 + (lane&15); chunk = ks*2 + (lane>>4)
    //   B: row = wn*32 + p*16   + (lane&15); chunk = ks*2 + (lane>>4)
    // swizzle: chunk ^= (row & 7) == (lane & 7)
    const int lrow = lane & 15;
    const int lhi = lane >> 4;
    const int lsw = lane & 7;
    const uint32_t a_row_off = (uint32_t)(wm * 64 + lrow) * 128u;
    const uint32_t b_row_off = (uint32_t)A_STAGE_BYTES + (uint32_t)(wn * 32 + lrow) * 128u;

    #pragma unroll
    for (int ps = 0; ps < STAGES - 1; ps++) {
        load_stage(ps, ps);
        cp_commit();
    }

    int cstage = 0, fstage = STAGES - 1;
    for (int c = 0; c < NCHUNK; c++) {
        cp_wait<STAGES - 2>();
        __syncthreads();

        const int fetch = c + STAGES - 1;
        if (fetch < NCHUNK) load_stage(fstage, fetch);
        cp_commit();
        if (++fstage == STAGES) fstage = 0;

        const uint32_t sbase = sb + (uint32_t)cstage * STAGE_BYTES;
        if (++cstage == STAGES) cstage = 0;

        #pragma unroll
        for (int ks = 0; ks < 4; ks++) {
            const uint32_t chunk = (uint32_t)(((ks * 2 + lhi) ^ lsw) * 16);
            uint32_t a[4][4];
            #pragma unroll
            for (int mi = 0; mi < 4; mi++)
                ldsm_x4(a[mi], sbase + a_row_off + (uint32_t)(mi * 16 * 128) + chunk);
            uint32_t b[2][4];
            #pragma unroll
            for (int p = 0; p < 2; p++)
                ldsm_x4(b[p], sbase + b_row_off + (uint32_t)(p * 16 * 128) + chunk);
            // b[p] regs: {n-tile(2p).b0, n-tile(2p+1).b0, n-tile(2p).b1, n-tile(2p+1).b1}
            #pragma unroll
            for (int mi = 0; mi < 4; mi++) {
                mma_f16(acc[mi][0], a[mi], b[0][0], b[0][2]);
                mma_f16(acc[mi][1], a[mi], b[0][1], b[0][3]);
                mma_f16(acc[mi][2], a[mi], b[1][0], b[1][2]);
                mma_f16(acc[mi][3], a[mi], b[1][1], b[1][3]);
            }
        }
        __syncthreads();
    }

    // ---------------- epilogue ----------------
    #pragma unroll
    for (int mi = 0; mi < 4; mi++) {
        const int row = m0 + wm * 64 + mi * 16 + g;
        #pragma unroll
        for (int ni = 0; ni < 4; ni++) {
            const int col = n0 + wn * 32 + ni * 8 + 2 * tig;
            float2 lo = make_float2(acc[mi][ni][0], acc[mi][ni][1]);
            float2 hi = make_float2(acc[mi][ni][2], acc[mi][ni][3]);
            *reinterpret_cast<float2*>(out + (size_t)row * N_DIM + col) = lo;
            *reinterpret_cast<float2*>(out + (size_t)(row + 8) * N_DIM + col) = hi;
        }
    }
}

extern "C" void kernel_launch(void* const* d_in, const int* in_sizes, int n_in,
                              void* d_out, int out_size) {
    const float* A_in = (const float*)d_in[0];   // [8,1024,4096] = [8192,4096]
    const float* W_in = (const float*)d_in[1];   // [4096,4096] K-major
    float* out = (float*)d_out;

    void *pA = nullptr, *pB = nullptr;
    cudaGetSymbolAddress(&pA, g_A);
    cudaGetSymbolAddress(&pB, g_B);

    cudaFuncSetAttribute(agg_gemm_kernel,
                         cudaFuncAttributeMaxDynamicSharedMemorySize, SMEM_BYTES);

    cvt_f16_kernel<<<1184, 256>>>((const float4*)A_in, (__half2*)pA,
                                  (int)(((size_t)M_DIM * K_DIM) / 4));
    cvt_f16_kernel<<<1184, 256>>>((const float4*)W_in, (__half2*)pB,
                                  (int)(((size_t)N_DIM * K_DIM) / 4));

    dim3 grid(N_DIM / BN, M_DIM / BM);   // (32, 64)
    agg_gemm_kernel<<<grid, 256, SMEM_BYTES>>>((const __half*)pA, (const __half*)pB, out);
}